// round 2
// baseline (speedup 1.0000x reference)
#include <cuda_runtime.h>
#include <cstdint>
#include <cstddef>

// ---------------------------------------------------------------------------
// Problem constants (from reference)
// ---------------------------------------------------------------------------
#define LOG_GAMMA  0.019802627296179713f     // ln(1.02)
#define ALPHA_     (-1.005033585350145e-05f) // ln(0.99)/1000
#define INIT_LOGW  (-1.3943265389999528f)    // ln(0.248)
#define INIT_LOGP  (-6.907755278982137f)     // ln(0.001)
#define INV_TEMP   (0.001f)                  // 1/1000
#define EPS_       (1e-12f)
#define LOG_EPS_   (-27.631021115928547f)    // ln(1e-12)
// Firing impossible once c_t < ~2.16e-9; 1e-10 = safe margin.
#define CUT_       (1e-10f)

#define MAXT_CAP 12288
#define NB_CAP   1024

__device__ float g_d[MAXT_CAP];       // d_t = LOG_GAMMA + log1p(-exp(a_t))
__device__ float g_c[MAXT_CAP];       // c_t = exp(logit_t) - eps
__device__ float g_thr[MAXT_CAP];     // u2 screen threshold (u2 <= thr => no fire)
__device__ float g_R[MAXT_CAP + 1];   // exclusive prefix sums of r_t
__device__ int   g_tcut;              // first t with c_t < CUT_
__device__ float g_bsum[NB_CAP];      // per-block partial sums

// ---------------------------------------------------------------------------
// Kernel 0 (wide): the only expensive transcendental, parallel over the chip.
// ---------------------------------------------------------------------------
__global__ void __launch_bounds__(256, 8)
dinit_kernel(const float* __restrict__ acts, int T) {
    int i = blockIdx.x * 256 + threadIdx.x;
    if (i < T) g_d[i] = LOG_GAMMA + log1pf(-__expf(acts[i]));
}

// ---------------------------------------------------------------------------
// Block-wide exclusive scan, 1024 threads fixed. sh must hold >= 32 floats.
// ---------------------------------------------------------------------------
__device__ __forceinline__ float block_exscan_1024(float v, float* sh) {
    const int lane = threadIdx.x & 31;
    const int wid  = threadIdx.x >> 5;
    float inc = v;
#pragma unroll
    for (int o = 1; o < 32; o <<= 1) {
        float n = __shfl_up_sync(0xffffffffu, inc, o);
        if (lane >= o) inc += n;
    }
    if (lane == 31) sh[wid] = inc;
    __syncthreads();
    if (wid == 0) {
        float wv = sh[lane];
        float wi = wv;
#pragma unroll
        for (int o = 1; o < 32; o <<= 1) {
            float n = __shfl_up_sync(0xffffffffu, wi, o);
            if (lane >= o) wi += n;
        }
        sh[lane] = wi - wv;  // warp-exclusive offsets
    }
    __syncthreads();
    float res = sh[wid] + (inc - v);
    __syncthreads();  // sh reusable by next scan
    return res;
}

// ---------------------------------------------------------------------------
// Kernel 1 (1 block, 1024 threads): chained scans, NO register arrays.
// Every pass recomputes its running prefix from g_d (L1-hot) / acts.
// ---------------------------------------------------------------------------
__global__ void __launch_bounds__(1024, 1)
precompute_kernel(const float* __restrict__ acts, int T) {
    __shared__ float sh[32];
    const int tid = threadIdx.x;
    if (tid == 0) g_tcut = T;   // ordered before atomicMin by scan barriers
    const int PT = (T + 1023) >> 10;
    const int i0 = tid * PT;

    // pass 1: local sum of d
    float run = 0.f;
    for (int j = 0; j < PT; j++) {
        int i = i0 + j;
        if (i < T) run += g_d[i];
    }
    const float woff = block_exscan_1024(run, sh);

    // pass 2: local sum of e_t = ALPHA * exp(a_t + logw_t)
    float erun = 0.f, dp = 0.f;
    for (int j = 0; j < PT; j++) {
        int i = i0 + j;
        if (i < T) {
            float wb = INIT_LOGW + woff + dp;           // logw before step i
            erun += ALPHA_ * __expf(acts[i] + wb);
            dp   += g_d[i];
        }
    }
    const float eoff = block_exscan_1024(erun, sh);

    // pass 3: c_t, thr_t, local sum of r_t
    float rrun = 0.f, ep = 0.f;
    dp = 0.f;
    for (int j = 0; j < PT; j++) {
        int i = i0 + j;
        if (i < T) {
            float dj   = g_d[i];
            float wb   = INIT_LOGW + woff + dp;
            float logp = INIT_LOGP + eoff + ep;
            float p    = __expf(logp);
            float c    = __fdividef(p, 1.0f - p) - EPS_;
            g_c[i]   = c;
            g_thr[i] = __expf(LOG_EPS_ * c) * (1.0f - 1e-5f);  // safe screen
            if (!(c >= CUT_)) atomicMin(&g_tcut, i);           // NaN-safe
            ep   += ALPHA_ * __expf(acts[i] + wb);
            rrun += __expf((wb + dj) * INV_TEMP);
            dp   += dj;
        }
    }
    const float roff = block_exscan_1024(rrun, sh);

    // pass 4: write exclusive prefix R
    float rp = 0.f;
    dp = 0.f;
    for (int j = 0; j < PT; j++) {
        int i = i0 + j;
        if (i < T) {
            float dj = g_d[i];
            float wa = INIT_LOGW + woff + dp + dj;
            g_R[i] = roff + rp;
            rp += __expf(wa * INV_TEMP);
            dp += dj;
            if (i == T - 1) g_R[T] = roff + rp;
        }
    }
}

// ---------------------------------------------------------------------------
// Kernel 2: per-batch first-fire search with u2-only screening.
// Block = 32 batch lanes x 32 warps over t, unroll 4 -> 128 t/iter.
// fired  <=>  log(u2+eps) > c_t * log(u1+eps); impossible when u2 <= thr_t.
// ---------------------------------------------------------------------------
__global__ void __launch_bounds__(1024, 1)
mainscan_kernel(const float* __restrict__ u1, const float* __restrict__ u2,
                int T, int BATCH) {
    __shared__ int sh_first[32];
    const int tid  = threadIdx.x;
    const int lane = tid & 31;
    const int w    = tid >> 5;
    const int b    = blockIdx.x * 32 + lane;
    const bool bvalid = (b < BATCH);

    if (tid < 32) sh_first[tid] = T;
    const int tcut = g_tcut;
    __syncthreads();

    const size_t sB = (size_t)BATCH;

    for (int base = 0; base < tcut; base += 128) {
        float x2[4], th[4];
        int   tt[4];
#pragma unroll
        for (int j = 0; j < 4; j++) {
            int t = base + w + 32 * j;
            tt[j] = t;
            bool v = (t < tcut) && bvalid;
            x2[j] = v ? __ldg(&u2[(size_t)t * sB + (size_t)b]) : 0.f;
            th[j] = (t < tcut) ? g_thr[t] : 2.f;
        }
#pragma unroll
        for (int j = 0; j < 4; j++) {
            if (x2[j] > th[j]) {  // rare: ~3% of elements
                float c  = g_c[tt[j]];
                float x1 = __ldg(&u1[(size_t)tt[j] * sB + (size_t)b]);
                if (__logf(x2[j] + EPS_) > c * __logf(x1 + EPS_))
                    atomicMin(&sh_first[lane], tt[j]);
            }
        }
    }
    __syncthreads();

    if (w == 0) {
        float val = bvalid ? g_R[sh_first[lane]] : 0.f;  // R[k_b] (k=T if none)
#pragma unroll
        for (int o = 16; o > 0; o >>= 1)
            val += __shfl_down_sync(0xffffffffu, val, o);
        if (lane == 0) g_bsum[blockIdx.x] = val;
    }
}

// ---------------------------------------------------------------------------
// Kernel 3: deterministic final reduction + mean.
// ---------------------------------------------------------------------------
__global__ void __launch_bounds__(128, 1)
reduce_kernel(float* __restrict__ out, int nb, float inv_batch) {
    __shared__ float sh[4];
    const int tid = threadIdx.x;
    float v = 0.f;
    for (int i = tid; i < nb; i += 128) v += g_bsum[i];
#pragma unroll
    for (int o = 16; o > 0; o >>= 1)
        v += __shfl_down_sync(0xffffffffu, v, o);
    if ((tid & 31) == 0) sh[tid >> 5] = v;
    __syncthreads();
    if (tid == 0) out[0] = (sh[0] + sh[1] + sh[2] + sh[3]) * inv_batch;
}

// ---------------------------------------------------------------------------
extern "C" void kernel_launch(void* const* d_in, const int* in_sizes, int n_in,
                              void* d_out, int out_size) {
    const float* acts = (const float*)d_in[0];
    const float* u1   = (const float*)d_in[1];
    const float* u2   = (const float*)d_in[2];
    int T = in_sizes[0];
    if (T > MAXT_CAP) T = MAXT_CAP;  // defensive; problem shape is T=10000
    int BATCH = in_sizes[1] / in_sizes[0];
    int nb = (BATCH + 31) / 32;
    if (nb > NB_CAP) nb = NB_CAP;

    dinit_kernel<<<(T + 255) / 256, 256>>>(acts, T);
    precompute_kernel<<<1, 1024>>>(acts, T);
    mainscan_kernel<<<nb, 1024>>>(u1, u2, T, BATCH);
    reduce_kernel<<<1, 128>>>((float*)d_out, nb, 1.0f / (float)BATCH);
}